// round 13
// baseline (speedup 1.0000x reference)
#include <cuda_runtime.h>
#include <cstdint>

#define INC   32
#define INN   50000
#define OUTC  32
#define OUTN  8192
#define MAXD  16
#define NB    8
#define NC    256   // N * INC
#define TILE_O 16

#define RING   3
#define RPS    8            // rows per stage (half of one o's 16 neighbors)
#define STAGES (TILE_O * 2) // 32 half-o stages
#define STAGE_BYTES (RPS * NC * 4)  // 8 KB

// 51.2 MB scratch for the transposed embedding table xT[i][n*32+c] = x[n][c][i]
__device__ float g_xT[(size_t)INN * NC];

// ---------------------------------------------------------------------------
// PTX helpers
// ---------------------------------------------------------------------------
static __device__ __forceinline__ uint32_t smem_u32(const void* p) {
    return (uint32_t)__cvta_generic_to_shared(p);
}
static __device__ __forceinline__ void mbar_init(uint32_t a, uint32_t cnt) {
    asm volatile("mbarrier.init.shared.b64 [%0], %1;" :: "r"(a), "r"(cnt) : "memory");
}
static __device__ __forceinline__ void mbar_expect_tx(uint32_t a, uint32_t bytes) {
    asm volatile("mbarrier.arrive.expect_tx.shared.b64 _, [%0], %1;"
                 :: "r"(a), "r"(bytes) : "memory");
}
static __device__ __forceinline__ void mbar_arrive(uint32_t a) {
    asm volatile("mbarrier.arrive.shared.b64 _, [%0];" :: "r"(a) : "memory");
}
// wait(p): returns when the barrier's phase bit != p  (fresh barrier: phase 0)
static __device__ __forceinline__ void mbar_wait(uint32_t a, uint32_t phase) {
    asm volatile(
        "{\n\t"
        ".reg .pred P;\n\t"
        "WAIT_%=:\n\t"
        "mbarrier.try_wait.parity.acquire.cta.shared::cta.b64 P, [%0], %1, 0x989680;\n\t"
        "@P bra.uni DONE_%=;\n\t"
        "bra.uni WAIT_%=;\n\t"
        "DONE_%=:\n\t"
        "}"
        :: "r"(a), "r"(phase) : "memory");
}
static __device__ __forceinline__ void bulk_g2s(uint32_t dst, const void* src,
                                                uint32_t bytes, uint32_t mbar) {
    asm volatile(
        "cp.async.bulk.shared::cluster.global.mbarrier::complete_tx::bytes "
        "[%0], [%1], %2, [%3];"
        :: "r"(dst), "l"(src), "r"(bytes), "r"(mbar) : "memory");
}

// ---------------------------------------------------------------------------
// Kernel 1: tiled transpose x [256 rows x 50000 cols] -> g_xT [50000 x 256]
// (measured ~17.5us, near memory ceiling — unchanged)
// ---------------------------------------------------------------------------
__global__ __launch_bounds__(256) void transpose_kernel(const float* __restrict__ x) {
    __shared__ float tile[32][33];
    const int i0 = blockIdx.x * 32;
    const int r0 = blockIdx.y * 32;
    const int tx = threadIdx.x;
    const int ty = threadIdx.y;

    #pragma unroll
    for (int k = 0; k < 32; k += 8) {
        const int i = i0 + tx;
        const int r = r0 + ty + k;
        tile[ty + k][tx] = (i < INN) ? x[(size_t)r * INN + i] : 0.0f;
    }
    __syncthreads();
    #pragma unroll
    for (int k = 0; k < 32; k += 8) {
        const int i = i0 + ty + k;
        if (i < INN)
            g_xT[(size_t)i * NC + (r0 + tx)] = tile[tx][ty + k];
    }
}

// ---------------------------------------------------------------------------
// Kernel 2: bulk-DMA gather pipeline + pool + matmul + bias.
//   Producer (tid 0): for each stage (half-o: 8 neighbor rows, 8 KB), issues
//     8 x cp.async.bulk 1 KB row copies into a 3-slot smem ring, tracked by
//     mbarrier complete_tx.
//   Consumers (all 256): thread t owns scalar column t; per stage does 8 LDS
//     (bank = t%32, conflict-free) + 8 FMA; writes pooled_s[o][t] after the
//     second half. Phase B = R3-proven matmul+bias.
// ---------------------------------------------------------------------------
__global__ __launch_bounds__(256, 4) void pool_mm_kernel(
    const int*   __restrict__ A,
    const float* __restrict__ mask,
    const float* __restrict__ weight,
    const float* __restrict__ bias,
    float*       __restrict__ out)
{
    __shared__ __align__(128) float rows[RING][RPS][NC];   // 24 KB
    __shared__ float pooled_s[TILE_O][260];                // 16.6 KB
    __shared__ float w_s[INC * OUTC];                      // 4 KB
    __shared__ int   a_s[TILE_O * MAXD];                   // 1 KB
    __shared__ float m_s[TILE_O * MAXD];                   // 1 KB
    __shared__ __align__(8) uint64_t mbar[2 * RING];       // full[0..2], empty[3..5]

    const int tid    = threadIdx.x;
    const int o_base = blockIdx.x * TILE_O;

    a_s[tid] = A[o_base * MAXD + tid];
    m_s[tid] = mask[o_base * MAXD + tid];
    #pragma unroll
    for (int k = 0; k < 4; ++k)
        w_s[tid + k * 256] = weight[tid + k * 256];

    uint32_t full_a[RING], empty_a[RING];
    #pragma unroll
    for (int j = 0; j < RING; ++j) {
        full_a[j]  = smem_u32(&mbar[j]);
        empty_a[j] = smem_u32(&mbar[RING + j]);
    }
    if (tid == 0) {
        #pragma unroll
        for (int j = 0; j < RING; ++j) {
            mbar_init(full_a[j], 1);      // completed by expect_tx + 8 KB of tx
            mbar_init(empty_a[j], 256);   // all consumer threads arrive
        }
    }
    __syncthreads();

    // -- producer helper (tid 0 only) --
    auto issue = [&](int t) {
        const int j = t % RING;
        const int k = t / RING;
        mbar_wait(empty_a[j], (k & 1) ^ 1);        // use 0 passes immediately
        mbar_expect_tx(full_a[j], STAGE_BYTES);
        const int o  = t >> 1;
        const int d0 = (t & 1) * RPS;
        const uint32_t dst0 = smem_u32(&rows[j][0][0]);
        #pragma unroll
        for (int dd = 0; dd < RPS; ++dd) {
            const int idx = a_s[o * MAXD + d0 + dd];
            bulk_g2s(dst0 + dd * (NC * 4), &g_xT[(size_t)idx * NC],
                     NC * 4, full_a[j]);
        }
    };

    if (tid == 0) {
        issue(0); issue(1); issue(2);   // prologue: fill the ring
    }

    // -- main loop: consume stages in order --
    float carry = 0.0f;
    for (int s = 0; s < STAGES; ++s) {
        const int j = s % RING;
        const int k = s / RING;
        mbar_wait(full_a[j], k & 1);

        const int o = s >> 1;
        const int h = s & 1;
        float part = 0.0f;
        #pragma unroll
        for (int dd = 0; dd < RPS; ++dd)
            part += m_s[o * MAXD + h * RPS + dd] * rows[j][dd][tid];

        mbar_arrive(empty_a[j]);
        if (h == 0) carry = part;
        else        pooled_s[o][tid] = carry + part;

        if (tid == 0 && s + RING < STAGES)
            issue(s + RING);
    }
    __syncthreads();

    // ---- Phase B: shared-weight matmul + bias (R3-proven) ----
    const int o    = tid & (TILE_O - 1);   // 0..15
    const int n    = (tid >> 4) & 7;       // 0..7
    const int half = tid >> 7;             // 0..1 -> owns 16 outc

    float acc[16];
    #pragma unroll
    for (int k = 0; k < 16; ++k)
        acc[k] = bias[(size_t)(half * 16 + k) * OUTN + o_base + o];

    #pragma unroll
    for (int c = 0; c < INC; ++c) {
        const float p = pooled_s[o][n * 32 + c];
        #pragma unroll
        for (int k = 0; k < 16; ++k)
            acc[k] += p * w_s[c * 32 + half * 16 + k];   // broadcast
    }

    #pragma unroll
    for (int k = 0; k < 16; ++k)
        out[(size_t)(n * OUTC + half * 16 + k) * OUTN + o_base + o] = acc[k];
}

// ---------------------------------------------------------------------------
// Launch
// ---------------------------------------------------------------------------
extern "C" void kernel_launch(void* const* d_in, const int* in_sizes, int n_in,
                              void* d_out, int out_size)
{
    const float* x      = (const float*)d_in[0];  // [8, 32, 50000] f32
    const int*   A      = (const int*)  d_in[1];  // [8192, 16] i32
    const float* mask   = (const float*)d_in[2];  // [8192, 16, 1] f32
    const float* weight = (const float*)d_in[3];  // [32, 32] f32
    const float* bias   = (const float*)d_in[4];  // [32, 8192] f32
    float*       out    = (float*)d_out;          // [8, 32, 8192] f32

    dim3 tb(32, 8);
    dim3 tg((INN + 31) / 32, NC / 32);
    transpose_kernel<<<tg, tb>>>(x);

    pool_mm_kernel<<<OUTN / TILE_O, 256>>>(A, mask, weight, bias, out);
}

// round 14
// speedup vs baseline: 1.0982x; 1.0982x over previous
#include <cuda_runtime.h>
#include <cstdint>

#define INC   32
#define INN   50000
#define OUTC  32
#define OUTN  8192
#define MAXD  16
#define NB    8
#define NC    256   // N * INC
#define TILE_O 16

#define RPS    4                    // rows per stage
#define RING   4                    // smem ring slots
#define STAGES (TILE_O * MAXD / RPS) // 64

// 51.2 MB scratch for the transposed embedding table xT[i][n*32+c] = x[n][c][i]
__device__ float g_xT[(size_t)INN * NC];

static __device__ __forceinline__ uint32_t smem_u32(const void* p) {
    return (uint32_t)__cvta_generic_to_shared(p);
}
static __device__ __forceinline__ void cp16(uint32_t dst, const void* src) {
    asm volatile("cp.async.cg.shared.global [%0], [%1], 16;"
                 :: "r"(dst), "l"(src) : "memory");
}
static __device__ __forceinline__ void cp_commit() {
    asm volatile("cp.async.commit_group;" ::: "memory");
}
static __device__ __forceinline__ void cp_wait2() {
    asm volatile("cp.async.wait_group 2;" ::: "memory");
}

// ---------------------------------------------------------------------------
// Kernel 1: tiled transpose x [256 rows x 50000 cols] -> g_xT [50000 x 256]
// (measured ~17.5us, near memory ceiling — unchanged)
// ---------------------------------------------------------------------------
__global__ __launch_bounds__(256) void transpose_kernel(const float* __restrict__ x) {
    __shared__ float tile[32][33];
    const int i0 = blockIdx.x * 32;
    const int r0 = blockIdx.y * 32;
    const int tx = threadIdx.x;
    const int ty = threadIdx.y;

    #pragma unroll
    for (int k = 0; k < 32; k += 8) {
        const int i = i0 + tx;
        const int r = r0 + ty + k;
        tile[ty + k][tx] = (i < INN) ? x[(size_t)r * INN + i] : 0.0f;
    }
    __syncthreads();
    #pragma unroll
    for (int k = 0; k < 32; k += 8) {
        const int i = i0 + ty + k;
        if (i < INN)
            g_xT[(size_t)i * NC + (r0 + tx)] = tile[tx][ty + k];
    }
}

// ---------------------------------------------------------------------------
// Kernel 2: all-thread cp.async gather pipeline + pool + matmul + bias.
//   Stage = 4 neighbor rows (4 KB). Each thread copies ONE 16B chunk per
//   stage (row dd = tid>>6, chunk = tid&63), commit_group per stage.
//   Ring of 4 slots, 3 groups in flight, wait_group(2) + one bar.sync per
//   stage. Tail issues empty commit_groups so the outstanding count stays 3.
//   Consumer: thread t reads column t of the 4 rows (bank t%32, conflict-
//   free), accumulates with mask; after 4 stages (one o) writes pooled_s.
//   Phase B = R3-proven matmul + bias.
// ---------------------------------------------------------------------------
__global__ __launch_bounds__(256, 5) void pool_mm_kernel(
    const int*   __restrict__ A,
    const float* __restrict__ mask,
    const float* __restrict__ weight,
    const float* __restrict__ bias,
    float*       __restrict__ out)
{
    __shared__ __align__(128) float rows[RING][RPS][NC];   // 16 KB
    __shared__ float pooled_s[TILE_O][260];                // 16.6 KB
    __shared__ float w_s[INC * OUTC];                      // 4 KB
    __shared__ int   a_s[TILE_O * MAXD];                   // 1 KB
    __shared__ float m_s[TILE_O * MAXD];                   // 1 KB

    const int tid    = threadIdx.x;
    const int o_base = blockIdx.x * TILE_O;

    a_s[tid] = A[o_base * MAXD + tid];
    m_s[tid] = mask[o_base * MAXD + tid];
    #pragma unroll
    for (int k = 0; k < 4; ++k)
        w_s[tid + k * 256] = weight[tid + k * 256];
    __syncthreads();   // a_s ready before any issue

    // per-thread copy coordinates: row dd = tid>>6 (0..3), 16B chunk = tid&63
    const int dd_i  = tid >> 6;
    const int chunk = (tid & 63) * 4;     // float offset of this thread's 16B
    const uint32_t dst_base = smem_u32(&rows[0][0][0]);

    // issue one stage s into slot s%RING (1 cp.async + commit per thread)
    auto issue = [&](int s) {
        const int idx = a_s[s * RPS + dd_i];    // s*RPS+dd spans o*MAXD+d linearly
        cp16(dst_base + (((s % RING) * RPS + dd_i) * NC + chunk) * 4,
             &g_xT[(size_t)idx * NC + chunk]);
        cp_commit();
    };

    issue(0); issue(1); issue(2);   // prologue: 3 groups in flight

    float carry = 0.0f;
    for (int s = 0; s < STAGES; ++s) {
        cp_wait2();          // own groups: stage s complete
        __syncthreads();     // everyone's stage-s data visible; slot (s-1)%RING free

        if (s + 3 < STAGES) issue(s + 3);
        else                cp_commit();       // empty group keeps count at 3

        const int j   = s % RING;
        const int o   = s >> 2;
        const int sub = s & 3;
        float part = 0.0f;
        #pragma unroll
        for (int dd = 0; dd < RPS; ++dd)
            part += m_s[o * MAXD + sub * RPS + dd] * rows[j][dd][tid];

        carry = (sub == 0) ? part : carry + part;
        if (sub == 3)
            pooled_s[o][tid] = carry;
    }
    __syncthreads();

    // ---- Phase B: shared-weight matmul + bias (R3-proven) ----
    const int o    = tid & (TILE_O - 1);   // 0..15
    const int n    = (tid >> 4) & 7;       // 0..7
    const int half = tid >> 7;             // 0..1 -> owns 16 outc

    float acc[16];
    #pragma unroll
    for (int k = 0; k < 16; ++k)
        acc[k] = bias[(size_t)(half * 16 + k) * OUTN + o_base + o];

    #pragma unroll
    for (int c = 0; c < INC; ++c) {
        const float p = pooled_s[o][n * 32 + c];
        #pragma unroll
        for (int k = 0; k < 16; ++k)
            acc[k] += p * w_s[c * 32 + half * 16 + k];   // broadcast
    }

    #pragma unroll
    for (int k = 0; k < 16; ++k)
        out[(size_t)(n * OUTC + half * 16 + k) * OUTN + o_base + o] = acc[k];
}

// ---------------------------------------------------------------------------
// Launch
// ---------------------------------------------------------------------------
extern "C" void kernel_launch(void* const* d_in, const int* in_sizes, int n_in,
                              void* d_out, int out_size)
{
    const float* x      = (const float*)d_in[0];  // [8, 32, 50000] f32
    const int*   A      = (const int*)  d_in[1];  // [8192, 16] i32
    const float* mask   = (const float*)d_in[2];  // [8192, 16, 1] f32
    const float* weight = (const float*)d_in[3];  // [32, 32] f32
    const float* bias   = (const float*)d_in[4];  // [32, 8192] f32
    float*       out    = (float*)d_out;          // [8, 32, 8192] f32

    dim3 tb(32, 8);
    dim3 tg((INN + 31) / 32, NC / 32);
    transpose_kernel<<<tg, tb>>>(x);

    pool_mm_kernel<<<OUTN / TILE_O, 256>>>(A, mask, weight, bias, out);
}

// round 15
// speedup vs baseline: 1.7154x; 1.5620x over previous
#include <cuda_runtime.h>
#include <cuda_fp16.h>
#include <cstdint>

#define INC   32
#define INN   50000
#define OUTC  32
#define OUTN  8192
#define MAXD  16
#define NB    8
#define NC    256   // N * INC
#define TILE_O 16

// 25.6 MB scratch: fp16 transposed table xTh[i][n*32+c] = (half)x[n][c][i]
__device__ __half g_xTh[(size_t)INN * NC];

// ---------------------------------------------------------------------------
// Kernel 1: tiled transpose + fp16 quantize.
//   x [256 rows x 50000 cols] f32 -> g_xTh [50000 x 256] fp16.
//   Same R3-proven tiling; store side writes __half (64B/warp, halved bytes).
// ---------------------------------------------------------------------------
__global__ __launch_bounds__(256) void transpose_kernel(const float* __restrict__ x) {
    __shared__ float tile[32][33];
    const int i0 = blockIdx.x * 32;
    const int r0 = blockIdx.y * 32;
    const int tx = threadIdx.x;
    const int ty = threadIdx.y;

    #pragma unroll
    for (int k = 0; k < 32; k += 8) {
        const int i = i0 + tx;
        const int r = r0 + ty + k;       // r < 256 always (gridDim.y = 8)
        tile[ty + k][tx] = (i < INN) ? x[(size_t)r * INN + i] : 0.0f;
    }
    __syncthreads();
    #pragma unroll
    for (int k = 0; k < 32; k += 8) {
        const int i = i0 + ty + k;
        if (i < INN)
            g_xTh[(size_t)i * NC + (r0 + tx)] = __float2half(tile[tx][ty + k]);
    }
}

// ---------------------------------------------------------------------------
// Kernel 2: R3-proven structure, fp16 gathers.
//   Phase A: thread (o_sub = tid>>6, col = tid&63) pools one 4-element column
//     over 16 neighbors per o-group. Row = 512 B; per-thread load = uint2
//     (4 halves, LDG.64), fp32 accumulate.
//   Phase B: unchanged matmul + bias, coalesced stores.
// ---------------------------------------------------------------------------
__global__ __launch_bounds__(256, 4) void pool_mm_kernel(
    const int*   __restrict__ A,
    const float* __restrict__ mask,
    const float* __restrict__ weight,
    const float* __restrict__ bias,
    float*       __restrict__ out)
{
    __shared__ float pooled_s[TILE_O][260];   // [o][r]
    __shared__ float w_s[INC * OUTC];
    __shared__ int   a_s[TILE_O * MAXD];      // 256
    __shared__ float m_s[TILE_O * MAXD];      // 256

    const int tid    = threadIdx.x;
    const int o_base = blockIdx.x * TILE_O;

    a_s[tid] = A[o_base * MAXD + tid];
    m_s[tid] = mask[o_base * MAXD + tid];
    #pragma unroll
    for (int k = 0; k < 4; ++k)
        w_s[tid + k * 256] = weight[tid + k * 256];
    __syncthreads();

    // ---- Phase A: fp16 gather + masked pool ----
    const uint2* __restrict__ z2 = (const uint2*)g_xTh;  // 4 halves per uint2
    const int o_sub = tid >> 6;      // 0..3
    const int col   = tid & 63;      // 4-half column of the 256-half row

    #pragma unroll
    for (int g = 0; g < TILE_O / 4; ++g) {
        const int o = g * 4 + o_sub;
        float4 acc = make_float4(0.f, 0.f, 0.f, 0.f);
        #pragma unroll
        for (int d = 0; d < MAXD; ++d) {
            const int   idx = a_s[o * MAXD + d];                 // broadcast
            const float m   = m_s[o * MAXD + d];                 // broadcast
            const uint2 raw = z2[(size_t)idx * (NC / 4) + col];  // LDG.64
            const float2 lo = __half22float2(*(const __half2*)&raw.x);
            const float2 hi = __half22float2(*(const __half2*)&raw.y);
            acc.x += m * lo.x; acc.y += m * lo.y;
            acc.z += m * hi.x; acc.w += m * hi.y;
        }
        *(float4*)&pooled_s[o][col * 4] = acc;                   // conflict-free
    }
    __syncthreads();

    // ---- Phase B: shared-weight matmul + bias (R3-proven) ----
    const int o    = tid & (TILE_O - 1);   // 0..15
    const int n    = (tid >> 4) & 7;       // 0..7
    const int half = tid >> 7;             // 0..1 -> owns 16 outc

    float acc[16];
    #pragma unroll
    for (int k = 0; k < 16; ++k)
        acc[k] = bias[(size_t)(half * 16 + k) * OUTN + o_base + o];

    #pragma unroll
    for (int c = 0; c < INC; ++c) {
        const float p = pooled_s[o][n * 32 + c];
        #pragma unroll
        for (int k = 0; k < 16; ++k)
            acc[k] += p * w_s[c * 32 + half * 16 + k];   // broadcast
    }

    #pragma unroll
    for (int k = 0; k < 16; ++k)
        out[(size_t)(n * OUTC + half * 16 + k) * OUTN + o_base + o] = acc[k];
}

// ---------------------------------------------------------------------------
// Launch
// ---------------------------------------------------------------------------
extern "C" void kernel_launch(void* const* d_in, const int* in_sizes, int n_in,
                              void* d_out, int out_size)
{
    const float* x      = (const float*)d_in[0];  // [8, 32, 50000] f32
    const int*   A      = (const int*)  d_in[1];  // [8192, 16] i32
    const float* mask   = (const float*)d_in[2];  // [8192, 16, 1] f32
    const float* weight = (const float*)d_in[3];  // [32, 32] f32
    const float* bias   = (const float*)d_in[4];  // [32, 8192] f32
    float*       out    = (float*)d_out;          // [8, 32, 8192] f32

    dim3 tb(32, 8);
    dim3 tg((INN + 31) / 32, NC / 32);
    transpose_kernel<<<tg, tb>>>(x);

    pool_mm_kernel<<<OUTN / TILE_O, 256>>>(A, mask, weight, bias, out);
}

// round 16
// speedup vs baseline: 2.1531x; 1.2551x over previous
#include <cuda_runtime.h>
#include <cuda_fp16.h>
#include <cstdint>

#define INC   32
#define INN   50000
#define OUTC  32
#define OUTN  8192
#define MAXD  16
#define NB    8
#define NC    256   // N * INC (halves per xT row)
#define TILE_O 16

// 25.6 MB scratch: fp16 transposed table xTh[i][n*32+c] = (half)x[n][c][i]
__device__ __half g_xTh[(size_t)INN * NC];

// ---------------------------------------------------------------------------
// Kernel 1: tiled transpose + fp16 quantize, vectorized stores.
//   Block: 32 i x 64 r (r = n*32+c). Load lanes vary i (128 B/warp reads);
//   store lanes pack __half2 over r (128 B/warp writes).
//   Smem tile_h[32][66]: write bank = (33*i + r/2)%32, lanes i -> CF;
//   read bank = (33*i + tx)%32, lanes tx -> CF; __half2 reads 4B-aligned.
// ---------------------------------------------------------------------------
__global__ __launch_bounds__(256) void transpose_kernel(const float* __restrict__ x) {
    __shared__ __half tile_h[32][66];
    const int i0 = blockIdx.x * 32;
    const int r0 = blockIdx.y * 64;
    const int tx = threadIdx.x;
    const int ty = threadIdx.y;

    #pragma unroll
    for (int k = 0; k < 64; k += 8) {
        const int rr = ty + k;           // 0..63
        const int i  = i0 + tx;
        const float v = (i < INN) ? x[(size_t)(r0 + rr) * INN + i] : 0.0f;
        tile_h[tx][rr] = __float2half(v);
    }
    __syncthreads();
    #pragma unroll
    for (int k = 0; k < 32; k += 8) {
        const int ii = ty + k;           // 0..31
        const int i  = i0 + ii;
        if (i < INN) {
            const __half2 v = *(const __half2*)&tile_h[ii][2 * tx];
            *(__half2*)&g_xTh[(size_t)i * NC + r0 + 2 * tx] = v;  // 128B/warp
        }
    }
}

// ---------------------------------------------------------------------------
// Kernel 2: fp16 gather + pool + matmul + bias, n-split for occupancy.
//   Grid (512, 2): blockIdx.y = nh picks half of each 512B row (4 n-values).
//   Phase A: thread (o_sub = tid>>5 in 0..7, col = tid&31) pools a 4-half
//     column over 16 neighbors for 2 o-groups (LDG.64, 256 B/warp coalesced).
//   Phase B: thread (q=tid>>6, n_=(tid>>4)&3, o=tid&15) -> 8 outc accums.
// ---------------------------------------------------------------------------
__global__ __launch_bounds__(256, 6) void pool_mm_kernel(
    const int*   __restrict__ A,
    const float* __restrict__ mask,
    const float* __restrict__ weight,
    const float* __restrict__ bias,
    float*       __restrict__ out)
{
    __shared__ float pooled_s[TILE_O][132];   // [o][n_*32+c], n_ local 0..3
    __shared__ float w_s[INC * OUTC];
    __shared__ int   a_s[TILE_O * MAXD];      // 256
    __shared__ float m_s[TILE_O * MAXD];      // 256

    const int tid    = threadIdx.x;
    const int o_base = blockIdx.x * TILE_O;
    const int nh     = blockIdx.y;            // 0/1: which 4-n half

    a_s[tid] = A[o_base * MAXD + tid];
    m_s[tid] = mask[o_base * MAXD + tid];
    #pragma unroll
    for (int k = 0; k < 4; ++k)
        w_s[tid + k * 256] = weight[tid + k * 256];
    __syncthreads();

    // ---- Phase A: fp16 gather + masked pool (half-row per block) ----
    const uint2* __restrict__ z2 = (const uint2*)g_xTh;  // 4 halves per uint2
    const int col   = tid & 31;               // uint2 column within half-row
    const int o_sub = tid >> 5;               // 0..7
    const int boff  = nh * 32 + col;          // uint2 offset in the 64-wide row

    #pragma unroll
    for (int g = 0; g < 2; ++g) {
        const int o = g * 8 + o_sub;
        float4 acc = make_float4(0.f, 0.f, 0.f, 0.f);
        #pragma unroll
        for (int d = 0; d < MAXD; ++d) {
            const int   idx = a_s[o * MAXD + d];               // broadcast
            const float m   = m_s[o * MAXD + d];               // broadcast
            const uint2 raw = z2[(size_t)idx * (NC / 4) + boff];  // LDG.64
            const float2 lo = __half22float2(*(const __half2*)&raw.x);
            const float2 hi = __half22float2(*(const __half2*)&raw.y);
            acc.x += m * lo.x; acc.y += m * lo.y;
            acc.z += m * hi.x; acc.w += m * hi.y;
        }
        *(float4*)&pooled_s[o][col * 4] = acc;   // contiguous 512B, CF
    }
    __syncthreads();

    // ---- Phase B: shared-weight matmul + bias (8 accumulators) ----
    const int o  = tid & (TILE_O - 1);   // 0..15
    const int n_ = (tid >> 4) & 3;       // 0..3 local n
    const int q  = tid >> 6;             // 0..3 -> owns outc [q*8, q*8+8)
    const int n  = nh * 4 + n_;

    float acc[8];
    #pragma unroll
    for (int k = 0; k < 8; ++k)
        acc[k] = bias[(size_t)(q * 8 + k) * OUTN + o_base + o];

    #pragma unroll
    for (int c = 0; c < INC; ++c) {
        const float p = pooled_s[o][n_ * 32 + c];   // 2-way conflict, negligible
        #pragma unroll
        for (int k = 0; k < 8; ++k)
            acc[k] += p * w_s[c * 32 + q * 8 + k];  // broadcast
    }

    #pragma unroll
    for (int k = 0; k < 8; ++k)
        out[(size_t)(n * OUTC + q * 8 + k) * OUTN + o_base + o] = acc[k];
}

// ---------------------------------------------------------------------------
// Launch
// ---------------------------------------------------------------------------
extern "C" void kernel_launch(void* const* d_in, const int* in_sizes, int n_in,
                              void* d_out, int out_size)
{
    const float* x      = (const float*)d_in[0];  // [8, 32, 50000] f32
    const int*   A      = (const int*)  d_in[1];  // [8192, 16] i32
    const float* mask   = (const float*)d_in[2];  // [8192, 16, 1] f32
    const float* weight = (const float*)d_in[3];  // [32, 32] f32
    const float* bias   = (const float*)d_in[4];  // [32, 8192] f32
    float*       out    = (float*)d_out;          // [8, 32, 8192] f32

    dim3 tb(32, 8);
    dim3 tg((INN + 31) / 32, NC / 64);
    transpose_kernel<<<tg, tb>>>(x);

    pool_mm_kernel<<<dim3(OUTN / TILE_O, 2), 256>>>(A, mask, weight, bias, out);
}